// round 1
// baseline (speedup 1.0000x reference)
#include <cuda_runtime.h>
#include <cuda_bf16.h>
#include <math.h>

// Problem constants (fixed by the dataset)
#define NN 50000
#define EE 800000
#define GG 8
#define IN_DIM 1792
#define HH 128
#define H3 384

// ---------------- scratch (static device memory; no allocs allowed) ----------------
__device__ float d_hp[(size_t)NN * H3];     // [h | h1 | h2]
__device__ float d_agg[(size_t)NN * HH];
__device__ float d_t[(size_t)NN * HH];
__device__ float d_Ga[(size_t)NN * H3];     // tanh(hp@Wa+ba)
__device__ float d_Gb[(size_t)NN * H3];     // sigmoid(hp@Wb+bb)
__device__ float d_s[NN];
__device__ float d_e[NN];
__device__ unsigned d_smaxu[GG];
__device__ float d_denom[GG];
__device__ float d_pooled[GG * H3];

// ---------------- generic SGEMM: C = act(A(+A2) @ W + bias) ----------------
// A: [M,K] row-major (lda), optional A2 added elementwise on load.
// W: [K,Ntot] row-major (ldw). Block tile 128x128, BK=8, 256 threads, 8x8 per thread.
#define BM 128
#define BN 128
#define BK 8
#define TM 8
#define TN 8

#define ACT_NONE 0
#define ACT_RELU 1
#define ACT_TANH 2
#define ACT_SIGM 3

template <int ACT>
__global__ __launch_bounds__(256) void sgemm_kernel(
    const float* __restrict__ A, int lda,
    const float* __restrict__ A2, int lda2,
    const float* __restrict__ W, int ldw,
    const float* __restrict__ bias,
    float* __restrict__ C, int ldc,
    int M, int K)
{
    __shared__ float As[BK][BM];
    __shared__ float Bs[BK][BN];

    const int tid = threadIdx.x;
    const int row0 = blockIdx.x * BM;
    const int col0 = blockIdx.y * BN;

    // A tile load map: 128x8 floats = 256 float4; row = tid/2, col = (tid&1)*4
    const int ar = tid >> 1;
    const int ac = (tid & 1) * 4;
    // B tile load map: 8x128 floats = 256 float4; row = tid/32, col = (tid&31)*4
    const int br = tid >> 5;
    const int bc = (tid & 31) * 4;

    const int tm = (tid >> 4) * TM;   // 0..120
    const int tn = (tid & 15) * TN;   // 0..120

    float acc[TM][TN];
#pragma unroll
    for (int i = 0; i < TM; i++)
#pragma unroll
        for (int j = 0; j < TN; j++) acc[i][j] = 0.f;

    const int nk = K / BK;
    const int am = row0 + ar;
    const bool a_ok = (am < M);

    for (int kt = 0; kt < nk; kt++) {
        float4 av = make_float4(0.f, 0.f, 0.f, 0.f);
        if (a_ok) {
            av = *(const float4*)(A + (size_t)am * lda + kt * BK + ac);
            if (A2) {
                float4 a2 = *(const float4*)(A2 + (size_t)am * lda2 + kt * BK + ac);
                av.x += a2.x; av.y += a2.y; av.z += a2.z; av.w += a2.w;
            }
        }
        float4 bv = *(const float4*)(W + (size_t)(kt * BK + br) * ldw + col0 + bc);

        __syncthreads();
        As[ac + 0][ar] = av.x;
        As[ac + 1][ar] = av.y;
        As[ac + 2][ar] = av.z;
        As[ac + 3][ar] = av.w;
        *(float4*)&Bs[br][bc] = bv;
        __syncthreads();

#pragma unroll
        for (int kk = 0; kk < BK; kk++) {
            float a[TM], b[TN];
#pragma unroll
            for (int i = 0; i < TM; i++) a[i] = As[kk][tm + i];
#pragma unroll
            for (int j = 0; j < TN; j++) b[j] = Bs[kk][tn + j];
#pragma unroll
            for (int i = 0; i < TM; i++)
#pragma unroll
                for (int j = 0; j < TN; j++) acc[i][j] = fmaf(a[i], b[j], acc[i][j]);
        }
    }

    // epilogue
    float bcache[TN];
#pragma unroll
    for (int j = 0; j < TN; j++) bcache[j] = bias[col0 + tn + j];

#pragma unroll
    for (int i = 0; i < TM; i++) {
        int m = row0 + tm + i;
        if (m < M) {
#pragma unroll
            for (int j4 = 0; j4 < TN; j4 += 4) {
                float4 v;
                float* vv = &v.x;
#pragma unroll
                for (int u = 0; u < 4; u++) {
                    float x = acc[i][j4 + u] + bcache[j4 + u];
                    if (ACT == ACT_RELU) x = fmaxf(x, 0.f);
                    else if (ACT == ACT_TANH) x = tanhf(x);
                    else if (ACT == ACT_SIGM) x = 1.f / (1.f + expf(-x));
                    vv[u] = x;
                }
                *(float4*)(C + (size_t)m * ldc + col0 + tn + j4) = v;
            }
        }
    }
}

// ---------------- edge scatter-add: agg[dst] += h[src] ----------------
// one lane = one float4 of one edge (32 lanes/edge cover 128 floats)
__global__ __launch_bounds__(256) void edge_agg_kernel(
    const int* __restrict__ src, const int* __restrict__ dst,
    const float* __restrict__ h, int ldh, float* __restrict__ agg)
{
    int i = blockIdx.x * blockDim.x + threadIdx.x;
    int e = i >> 5;
    int lane = i & 31;
    if (e >= EE) return;
    int s = src[e];
    int d = dst[e];
    float4 v = *(const float4*)(h + (size_t)s * ldh + lane * 4);
    float* p = agg + (size_t)d * HH + lane * 4;
    asm volatile("red.global.add.v4.f32 [%0], {%1,%2,%3,%4};"
                 :: "l"(p), "f"(v.x), "f"(v.y), "f"(v.z), "f"(v.w) : "memory");
}

// ---------------- score: s[i] = sum_j Ga[i][j]*Gb[i][j]*Wc[j] + bc ----------------
__global__ __launch_bounds__(256) void score_kernel(
    const float* __restrict__ Ga, const float* __restrict__ Gb,
    const float* __restrict__ Wc, const float* __restrict__ bc,
    float* __restrict__ s)
{
    int gwarp = (blockIdx.x * blockDim.x + threadIdx.x) >> 5;
    int lane = threadIdx.x & 31;
    if (gwarp >= NN) return;
    const float4* ga = (const float4*)(Ga + (size_t)gwarp * H3);
    const float4* gb = (const float4*)(Gb + (size_t)gwarp * H3);
    const float4* wc = (const float4*)Wc;
    float acc = 0.f;
#pragma unroll
    for (int k = 0; k < 3; k++) {
        int j = lane + k * 32;
        float4 a = ga[j], b = gb[j], w = wc[j];
        acc += a.x * b.x * w.x + a.y * b.y * w.y + a.z * b.z * w.z + a.w * b.w * w.w;
    }
#pragma unroll
    for (int o = 16; o; o >>= 1) acc += __shfl_xor_sync(0xffffffffu, acc, o);
    if (lane == 0) s[gwarp] = acc + bc[0];
}

// ordered-uint encoding for float atomicMax
__device__ __forceinline__ unsigned fenc(float v) {
    unsigned b = __float_as_uint(v);
    return (b & 0x80000000u) ? ~b : (b | 0x80000000u);
}
__device__ __forceinline__ float fdec(unsigned u) {
    return (u & 0x80000000u) ? __uint_as_float(u & 0x7fffffffu) : __uint_as_float(~u);
}

__global__ __launch_bounds__(256) void segmax_kernel(
    const float* __restrict__ s, const int* __restrict__ batch, unsigned* __restrict__ smaxu)
{
    __shared__ unsigned sm[GG];
    if (threadIdx.x < GG) sm[threadIdx.x] = 0u;
    __syncthreads();
    int i = blockIdx.x * blockDim.x + threadIdx.x;
    if (i < NN) atomicMax(&sm[batch[i]], fenc(s[i]));
    __syncthreads();
    if (threadIdx.x < GG) atomicMax(&smaxu[threadIdx.x], sm[threadIdx.x]);
}

__global__ __launch_bounds__(256) void expsum_kernel(
    const float* __restrict__ s, const int* __restrict__ batch,
    const unsigned* __restrict__ smaxu, float* __restrict__ e, float* __restrict__ denom)
{
    __shared__ float sd[GG];
    if (threadIdx.x < GG) sd[threadIdx.x] = 0.f;
    __syncthreads();
    int i = blockIdx.x * blockDim.x + threadIdx.x;
    if (i < NN) {
        int g = batch[i];
        float v = expf(s[i] - fdec(smaxu[g]));
        e[i] = v;
        atomicAdd(&sd[g], v);
    }
    __syncthreads();
    if (threadIdx.x < GG) atomicAdd(&denom[threadIdx.x], sd[threadIdx.x]);
}

// ---------------- pooled[g][c] = sum_i in g  hp[i][c] * w[i] ----------------
#define PROWS 128
__global__ __launch_bounds__(H3) void pool_kernel(
    const float* __restrict__ hp, const float* __restrict__ e,
    const float* __restrict__ denom, const int* __restrict__ batch,
    float* __restrict__ pooled)
{
    __shared__ float wsh[PROWS];
    __shared__ int gsh[PROWS];
    int r0 = blockIdx.x * PROWS;
    int nr = min(PROWS, NN - r0);
    int tid = threadIdx.x;
    if (tid < nr) {
        int g = batch[r0 + tid];
        gsh[tid] = g;
        wsh[tid] = e[r0 + tid] / denom[g];
    }
    __syncthreads();
    int c = tid;
    float acc = 0.f;
    int curg = gsh[0];
    for (int r = 0; r < nr; r++) {
        int g = gsh[r];
        if (g != curg) {
            atomicAdd(&pooled[curg * H3 + c], acc);
            acc = 0.f;
            curg = g;
        }
        acc += hp[(size_t)(r0 + r) * H3 + c] * wsh[r];
    }
    atomicAdd(&pooled[curg * H3 + c], acc);
}

// ---------------- head: out[g] = relu(pooled@Wr+br) @ Wk + bk ----------------
__global__ __launch_bounds__(H3) void head_kernel(
    const float* __restrict__ pooled, const float* __restrict__ Wr,
    const float* __restrict__ br, const float* __restrict__ Wk,
    const float* __restrict__ bk, float* __restrict__ out)
{
    __shared__ float ps[GG * H3];
    __shared__ float rs[GG * H3];
    int tid = threadIdx.x;
    for (int i = tid; i < GG * H3; i += H3) ps[i] = pooled[i];
    __syncthreads();
    int c = tid;
    float bias = br[c];
#pragma unroll 1
    for (int g = 0; g < GG; g++) {
        float a = 0.f;
        for (int k = 0; k < H3; k++) a = fmaf(ps[g * H3 + k], Wr[(size_t)k * H3 + c], a);
        rs[g * H3 + c] = fmaxf(a + bias, 0.f);
    }
    __syncthreads();
    int warp = tid >> 5, lane = tid & 31;
    if (warp < GG) {
        float a = 0.f;
        for (int j = lane; j < H3; j += 32) a += rs[warp * H3 + j] * Wk[j];
#pragma unroll
        for (int o = 16; o; o >>= 1) a += __shfl_xor_sync(0xffffffffu, a, o);
        if (lane == 0) out[warp] = a + bk[0];
    }
}

// ---------------- host ----------------
extern "C" void kernel_launch(void* const* d_in, const int* in_sizes, int n_in,
                              void* d_out, int out_size)
{
    const float* x      = (const float*)d_in[0];
    const int*   eidx   = (const int*)d_in[1];
    const int*   batch  = (const int*)d_in[2];
    const float* W_fc   = (const float*)d_in[3];
    const float* b_fc   = (const float*)d_in[4];
    const float* W1a    = (const float*)d_in[5];
    const float* b1a    = (const float*)d_in[6];
    const float* W1b    = (const float*)d_in[7];
    const float* b1b    = (const float*)d_in[8];
    const float* W2a    = (const float*)d_in[9];
    const float* b2a    = (const float*)d_in[10];
    const float* W2b    = (const float*)d_in[11];
    const float* b2b    = (const float*)d_in[12];
    const float* Wa     = (const float*)d_in[13];
    const float* ba     = (const float*)d_in[14];
    const float* Wb     = (const float*)d_in[15];
    const float* bb     = (const float*)d_in[16];
    const float* Wc     = (const float*)d_in[17];
    const float* bc     = (const float*)d_in[18];
    const float* Wr     = (const float*)d_in[19];
    const float* br     = (const float*)d_in[20];
    const float* Wk     = (const float*)d_in[21];
    const float* bk     = (const float*)d_in[22];
    float* out = (float*)d_out;

    const int* src = eidx;
    const int* dst = eidx + EE;

    float *hp, *agg, *t, *Ga, *Gb, *sS, *eE, *denom, *pooled;
    unsigned* smaxu;
    cudaGetSymbolAddress((void**)&hp, d_hp);
    cudaGetSymbolAddress((void**)&agg, d_agg);
    cudaGetSymbolAddress((void**)&t, d_t);
    cudaGetSymbolAddress((void**)&Ga, d_Ga);
    cudaGetSymbolAddress((void**)&Gb, d_Gb);
    cudaGetSymbolAddress((void**)&sS, d_s);
    cudaGetSymbolAddress((void**)&eE, d_e);
    cudaGetSymbolAddress((void**)&smaxu, d_smaxu);
    cudaGetSymbolAddress((void**)&denom, d_denom);
    cudaGetSymbolAddress((void**)&pooled, d_pooled);

    const int gmM = (NN + BM - 1) / BM;   // 391

    // 1) h = relu(x @ W_fc + b_fc)  -> hp[:, 0:128]
    sgemm_kernel<ACT_RELU><<<dim3(gmM, 1), 256>>>(
        x, IN_DIM, nullptr, 0, W_fc, HH, b_fc, hp, H3, NN, IN_DIM);

    // 2) GIN layer 1
    cudaMemsetAsync(agg, 0, (size_t)NN * HH * sizeof(float));
    edge_agg_kernel<<<(EE * 32) / 256, 256>>>(src, dst, hp, H3, agg);
    sgemm_kernel<ACT_RELU><<<dim3(gmM, 1), 256>>>(
        hp, H3, agg, HH, W1a, HH, b1a, t, HH, NN, HH);
    sgemm_kernel<ACT_RELU><<<dim3(gmM, 1), 256>>>(
        t, HH, nullptr, 0, W1b, HH, b1b, hp + HH, H3, NN, HH);

    // 3) GIN layer 2
    cudaMemsetAsync(agg, 0, (size_t)NN * HH * sizeof(float));
    edge_agg_kernel<<<(EE * 32) / 256, 256>>>(src, dst, hp + HH, H3, agg);
    sgemm_kernel<ACT_RELU><<<dim3(gmM, 1), 256>>>(
        hp + HH, H3, agg, HH, W2a, HH, b2a, t, HH, NN, HH);
    sgemm_kernel<ACT_RELU><<<dim3(gmM, 1), 256>>>(
        t, HH, nullptr, 0, W2b, HH, b2b, hp + 2 * HH, H3, NN, HH);

    // 4) gated attention scores
    sgemm_kernel<ACT_TANH><<<dim3(gmM, 3), 256>>>(
        hp, H3, nullptr, 0, Wa, H3, ba, Ga, H3, NN, H3);
    sgemm_kernel<ACT_SIGM><<<dim3(gmM, 3), 256>>>(
        hp, H3, nullptr, 0, Wb, H3, bb, Gb, H3, NN, H3);
    score_kernel<<<(NN * 32 + 255) / 256, 256>>>(Ga, Gb, Wc, bc, sS);

    // 5) segment softmax + weighted pooling
    cudaMemsetAsync(smaxu, 0, GG * sizeof(unsigned));
    cudaMemsetAsync(denom, 0, GG * sizeof(float));
    cudaMemsetAsync(pooled, 0, GG * H3 * sizeof(float));
    segmax_kernel<<<(NN + 255) / 256, 256>>>(sS, batch, smaxu);
    expsum_kernel<<<(NN + 255) / 256, 256>>>(sS, batch, smaxu, eE, denom);
    pool_kernel<<<(NN + PROWS - 1) / PROWS, H3>>>(hp, eE, denom, batch, pooled);

    // 6) head
    head_kernel<<<1, H3>>>(pooled, Wr, br, Wk, bk, out);
}

// round 2
// speedup vs baseline: 2.8969x; 2.8969x over previous
#include <cuda_runtime.h>
#include <cuda_bf16.h>
#include <math.h>

// Problem constants (fixed by the dataset)
#define NN 50000
#define EE 800000
#define GG 8
#define IN_DIM 1792
#define HH 128
#define H3 384

// ---------------- scratch (static device memory; no allocs allowed) ----------------
__device__ float d_hp[(size_t)NN * H3];     // [h | h1 | h2]
__device__ float d_agg[(size_t)NN * HH];
__device__ float d_t[(size_t)NN * HH];
__device__ float d_Ga[(size_t)NN * H3];     // tanh(hp@Wa+ba)
__device__ float d_Gb[(size_t)NN * H3];     // sigmoid(hp@Wb+bb)
__device__ float d_s[NN];
__device__ float d_e[NN];
__device__ unsigned d_smaxu[GG];
__device__ float d_denom[GG];
__device__ float d_pooled[GG * H3];

#define ACT_NONE 0
#define ACT_RELU 1
#define ACT_TANH 2
#define ACT_SIGM 3

// ---------------- tf32 tensor-core SGEMM ----------------
// C[M,N] = act((A (+A2)) @ W + bias)
// A row-major [M,K] (lda), W row-major [K,N] (ldw). N tile = 128 per blockIdx.y.
// Block: 256 thr = 8 warps (2 m x 4 n), warp tile 64x32, mma m16n8k8 tf32.

__device__ __forceinline__ unsigned f2tf(float x) {
    unsigned r;
    asm("cvt.rna.tf32.f32 %0, %1;" : "=r"(r) : "f"(x));
    return r;
}

__device__ __forceinline__ void mma_tf32(float* d, const unsigned* a, const unsigned* b) {
    asm volatile(
        "mma.sync.aligned.m16n8k8.row.col.f32.tf32.tf32.f32 "
        "{%0,%1,%2,%3}, {%4,%5,%6,%7}, {%8,%9}, {%0,%1,%2,%3};"
        : "+f"(d[0]), "+f"(d[1]), "+f"(d[2]), "+f"(d[3])
        : "r"(a[0]), "r"(a[1]), "r"(a[2]), "r"(a[3]), "r"(b[0]), "r"(b[1]));
}

#define AP 36    // As row stride in floats (A stored [m][k], 32 k + 4 pad)
#define BP 136   // Bs row stride in floats (B stored [k][n], 128 n + 8 pad)

template <int ACT>
__global__ __launch_bounds__(256, 2) void sgemm_tc(
    const float* __restrict__ A, int lda,
    const float* __restrict__ A2, int lda2,
    const float* __restrict__ W, int ldw,
    const float* __restrict__ bias,
    float* __restrict__ C, int ldc,
    int M, int K)
{
    __shared__ unsigned As[128 * AP];
    __shared__ unsigned Bs[32 * BP];

    const int tid = threadIdx.x;
    const int row0 = blockIdx.x * 128;
    const int col0 = blockIdx.y * 128;

    const int warp = tid >> 5;
    const int lane = tid & 31;
    const int group = lane >> 2;    // 0..7
    const int th4 = lane & 3;       // 0..3
    const int wm = (warp & 1) * 64;
    const int wn = (warp >> 1) * 32;

    // global->smem load maps
    const int la_r = tid >> 3;        // row within tile (0..31, +32*i)
    const int la_c = (tid & 7) * 4;   // k within tile (0..28)
    const int lb_r = tid >> 5;        // k within tile (0..7, +8*i)
    const int lb_c = (tid & 31) * 4;  // n within tile (0..124)

    float acc[4][4][4];
#pragma unroll
    for (int i = 0; i < 4; i++)
#pragma unroll
        for (int j = 0; j < 4; j++)
#pragma unroll
            for (int v = 0; v < 4; v++) acc[i][j][v] = 0.f;

    const int nk = K >> 5;

    float4 pa[4], pb[4];

    // prologue: load tile 0
#pragma unroll
    for (int i = 0; i < 4; i++) {
        int m = row0 + la_r + i * 32;
        if (m < M) {
            pa[i] = *(const float4*)(A + (size_t)m * lda + la_c);
            if (A2) {
                float4 t2 = *(const float4*)(A2 + (size_t)m * lda2 + la_c);
                pa[i].x += t2.x; pa[i].y += t2.y; pa[i].z += t2.z; pa[i].w += t2.w;
            }
        } else pa[i] = make_float4(0.f, 0.f, 0.f, 0.f);
        pb[i] = *(const float4*)(W + (size_t)(lb_r + i * 8) * ldw + col0 + lb_c);
    }

    for (int kt = 0; kt < nk; kt++) {
        __syncthreads();
#pragma unroll
        for (int i = 0; i < 4; i++) {
            int r = la_r + i * 32;
            As[r * AP + la_c + 0] = f2tf(pa[i].x);
            As[r * AP + la_c + 1] = f2tf(pa[i].y);
            As[r * AP + la_c + 2] = f2tf(pa[i].z);
            As[r * AP + la_c + 3] = f2tf(pa[i].w);
            uint4 bv;
            bv.x = f2tf(pb[i].x); bv.y = f2tf(pb[i].y);
            bv.z = f2tf(pb[i].z); bv.w = f2tf(pb[i].w);
            *(uint4*)&Bs[(lb_r + i * 8) * BP + lb_c] = bv;
        }
        __syncthreads();

        if (kt + 1 < nk) {
            int kb = (kt + 1) * 32;
#pragma unroll
            for (int i = 0; i < 4; i++) {
                int m = row0 + la_r + i * 32;
                if (m < M) {
                    pa[i] = *(const float4*)(A + (size_t)m * lda + kb + la_c);
                    if (A2) {
                        float4 t2 = *(const float4*)(A2 + (size_t)m * lda2 + kb + la_c);
                        pa[i].x += t2.x; pa[i].y += t2.y; pa[i].z += t2.z; pa[i].w += t2.w;
                    }
                } else pa[i] = make_float4(0.f, 0.f, 0.f, 0.f);
                pb[i] = *(const float4*)(W + (size_t)(kb + lb_r + i * 8) * ldw + col0 + lb_c);
            }
        }

#pragma unroll
        for (int ks = 0; ks < 4; ks++) {
            int kk = ks * 8;
            unsigned af[4][4], bf[4][2];
#pragma unroll
            for (int i = 0; i < 4; i++) {
                int mb = (wm + i * 16 + group) * AP + kk + th4;
                af[i][0] = As[mb];
                af[i][1] = As[mb + 8 * AP];
                af[i][2] = As[mb + 4];
                af[i][3] = As[mb + 8 * AP + 4];
            }
#pragma unroll
            for (int j = 0; j < 4; j++) {
                int nb = (kk + th4) * BP + wn + j * 8 + group;
                bf[j][0] = Bs[nb];
                bf[j][1] = Bs[nb + 4 * BP];
            }
#pragma unroll
            for (int i = 0; i < 4; i++)
#pragma unroll
                for (int j = 0; j < 4; j++)
                    mma_tf32(acc[i][j], af[i], bf[j]);
        }
    }

    // epilogue
#pragma unroll
    for (int i = 0; i < 4; i++) {
        int r0 = row0 + wm + i * 16 + group;
        int r1 = r0 + 8;
#pragma unroll
        for (int j = 0; j < 4; j++) {
            int cg = col0 + wn + j * 8 + th4 * 2;
            float b0 = bias[cg], b1 = bias[cg + 1];
            float v0 = acc[i][j][0] + b0, v1 = acc[i][j][1] + b1;
            float v2 = acc[i][j][2] + b0, v3 = acc[i][j][3] + b1;
            if (ACT == ACT_RELU) {
                v0 = fmaxf(v0, 0.f); v1 = fmaxf(v1, 0.f);
                v2 = fmaxf(v2, 0.f); v3 = fmaxf(v3, 0.f);
            } else if (ACT == ACT_TANH) {
                v0 = tanhf(v0); v1 = tanhf(v1); v2 = tanhf(v2); v3 = tanhf(v3);
            } else if (ACT == ACT_SIGM) {
                v0 = 1.f / (1.f + expf(-v0)); v1 = 1.f / (1.f + expf(-v1));
                v2 = 1.f / (1.f + expf(-v2)); v3 = 1.f / (1.f + expf(-v3));
            }
            if (r0 < M) { float2 o = make_float2(v0, v1); *(float2*)(C + (size_t)r0 * ldc + cg) = o; }
            if (r1 < M) { float2 o = make_float2(v2, v3); *(float2*)(C + (size_t)r1 * ldc + cg) = o; }
        }
    }
}

// ---------------- edge scatter-add: agg[dst] += h[src] ----------------
__global__ __launch_bounds__(256) void edge_agg_kernel(
    const int* __restrict__ src, const int* __restrict__ dst,
    const float* __restrict__ h, int ldh, float* __restrict__ agg)
{
    int i = blockIdx.x * blockDim.x + threadIdx.x;
    int e = i >> 5;
    int lane = i & 31;
    if (e >= EE) return;
    int s = src[e];
    int d = dst[e];
    float4 v = *(const float4*)(h + (size_t)s * ldh + lane * 4);
    float* p = agg + (size_t)d * HH + lane * 4;
    asm volatile("red.global.add.v4.f32 [%0], {%1,%2,%3,%4};"
                 :: "l"(p), "f"(v.x), "f"(v.y), "f"(v.z), "f"(v.w) : "memory");
}

// ---------------- score: s[i] = sum_j Ga[i][j]*Gb[i][j]*Wc[j] + bc ----------------
__global__ __launch_bounds__(256) void score_kernel(
    const float* __restrict__ Ga, const float* __restrict__ Gb,
    const float* __restrict__ Wc, const float* __restrict__ bc,
    float* __restrict__ s)
{
    int gwarp = (blockIdx.x * blockDim.x + threadIdx.x) >> 5;
    int lane = threadIdx.x & 31;
    if (gwarp >= NN) return;
    const float4* ga = (const float4*)(Ga + (size_t)gwarp * H3);
    const float4* gb = (const float4*)(Gb + (size_t)gwarp * H3);
    const float4* wc = (const float4*)Wc;
    float acc = 0.f;
#pragma unroll
    for (int k = 0; k < 3; k++) {
        int j = lane + k * 32;
        float4 a = ga[j], b = gb[j], w = wc[j];
        acc += a.x * b.x * w.x + a.y * b.y * w.y + a.z * b.z * w.z + a.w * b.w * w.w;
    }
#pragma unroll
    for (int o = 16; o; o >>= 1) acc += __shfl_xor_sync(0xffffffffu, acc, o);
    if (lane == 0) s[gwarp] = acc + bc[0];
}

// ordered-uint encoding for float atomicMax
__device__ __forceinline__ unsigned fenc(float v) {
    unsigned b = __float_as_uint(v);
    return (b & 0x80000000u) ? ~b : (b | 0x80000000u);
}
__device__ __forceinline__ float fdec(unsigned u) {
    return (u & 0x80000000u) ? __uint_as_float(u & 0x7fffffffu) : __uint_as_float(~u);
}

__global__ __launch_bounds__(256) void segmax_kernel(
    const float* __restrict__ s, const int* __restrict__ batch, unsigned* __restrict__ smaxu)
{
    __shared__ unsigned sm[GG];
    if (threadIdx.x < GG) sm[threadIdx.x] = 0u;
    __syncthreads();
    int i = blockIdx.x * blockDim.x + threadIdx.x;
    if (i < NN) atomicMax(&sm[batch[i]], fenc(s[i]));
    __syncthreads();
    if (threadIdx.x < GG) atomicMax(&smaxu[threadIdx.x], sm[threadIdx.x]);
}

__global__ __launch_bounds__(256) void expsum_kernel(
    const float* __restrict__ s, const int* __restrict__ batch,
    const unsigned* __restrict__ smaxu, float* __restrict__ e, float* __restrict__ denom)
{
    __shared__ float sd[GG];
    if (threadIdx.x < GG) sd[threadIdx.x] = 0.f;
    __syncthreads();
    int i = blockIdx.x * blockDim.x + threadIdx.x;
    if (i < NN) {
        int g = batch[i];
        float v = expf(s[i] - fdec(smaxu[g]));
        e[i] = v;
        atomicAdd(&sd[g], v);
    }
    __syncthreads();
    if (threadIdx.x < GG) atomicAdd(&denom[threadIdx.x], sd[threadIdx.x]);
}

// ---------------- pooled[g][c] = sum_i in g  hp[i][c] * w[i] ----------------
#define PROWS 128
__global__ __launch_bounds__(H3) void pool_kernel(
    const float* __restrict__ hp, const float* __restrict__ e,
    const float* __restrict__ denom, const int* __restrict__ batch,
    float* __restrict__ pooled)
{
    __shared__ float wsh[PROWS];
    __shared__ int gsh[PROWS];
    int r0 = blockIdx.x * PROWS;
    int nr = min(PROWS, NN - r0);
    int tid = threadIdx.x;
    if (tid < nr) {
        int g = batch[r0 + tid];
        gsh[tid] = g;
        wsh[tid] = e[r0 + tid] / denom[g];
    }
    __syncthreads();
    int c = tid;
    float acc = 0.f;
    int curg = gsh[0];
    for (int r = 0; r < nr; r++) {
        int g = gsh[r];
        if (g != curg) {
            atomicAdd(&pooled[curg * H3 + c], acc);
            acc = 0.f;
            curg = g;
        }
        acc += hp[(size_t)(r0 + r) * H3 + c] * wsh[r];
    }
    atomicAdd(&pooled[curg * H3 + c], acc);
}

// ---------------- head: out[g] = relu(pooled@Wr+br) @ Wk + bk ----------------
__global__ __launch_bounds__(H3) void head_kernel(
    const float* __restrict__ pooled, const float* __restrict__ Wr,
    const float* __restrict__ br, const float* __restrict__ Wk,
    const float* __restrict__ bk, float* __restrict__ out)
{
    __shared__ float ps[GG * H3];
    __shared__ float rs[GG * H3];
    int tid = threadIdx.x;
    for (int i = tid; i < GG * H3; i += H3) ps[i] = pooled[i];
    __syncthreads();
    int c = tid;
    float bias = br[c];
#pragma unroll 1
    for (int g = 0; g < GG; g++) {
        float a = 0.f;
        for (int k = 0; k < H3; k++) a = fmaf(ps[g * H3 + k], Wr[(size_t)k * H3 + c], a);
        rs[g * H3 + c] = fmaxf(a + bias, 0.f);
    }
    __syncthreads();
    int warp = tid >> 5, lane = tid & 31;
    if (warp < GG) {
        float a = 0.f;
        for (int j = lane; j < H3; j += 32) a += rs[warp * H3 + j] * Wk[j];
#pragma unroll
        for (int o = 16; o; o >>= 1) a += __shfl_xor_sync(0xffffffffu, a, o);
        if (lane == 0) out[warp] = a + bk[0];
    }
}

// ---------------- host ----------------
extern "C" void kernel_launch(void* const* d_in, const int* in_sizes, int n_in,
                              void* d_out, int out_size)
{
    const float* x      = (const float*)d_in[0];
    const int*   eidx   = (const int*)d_in[1];
    const int*   batch  = (const int*)d_in[2];
    const float* W_fc   = (const float*)d_in[3];
    const float* b_fc   = (const float*)d_in[4];
    const float* W1a    = (const float*)d_in[5];
    const float* b1a    = (const float*)d_in[6];
    const float* W1b    = (const float*)d_in[7];
    const float* b1b    = (const float*)d_in[8];
    const float* W2a    = (const float*)d_in[9];
    const float* b2a    = (const float*)d_in[10];
    const float* W2b    = (const float*)d_in[11];
    const float* b2b    = (const float*)d_in[12];
    const float* Wa     = (const float*)d_in[13];
    const float* ba     = (const float*)d_in[14];
    const float* Wb     = (const float*)d_in[15];
    const float* bb     = (const float*)d_in[16];
    const float* Wc     = (const float*)d_in[17];
    const float* bc     = (const float*)d_in[18];
    const float* Wr     = (const float*)d_in[19];
    const float* br     = (const float*)d_in[20];
    const float* Wk     = (const float*)d_in[21];
    const float* bk     = (const float*)d_in[22];
    float* out = (float*)d_out;

    const int* src = eidx;
    const int* dst = eidx + EE;

    float *hp, *agg, *t, *Ga, *Gb, *sS, *eE, *denom, *pooled;
    unsigned* smaxu;
    cudaGetSymbolAddress((void**)&hp, d_hp);
    cudaGetSymbolAddress((void**)&agg, d_agg);
    cudaGetSymbolAddress((void**)&t, d_t);
    cudaGetSymbolAddress((void**)&Ga, d_Ga);
    cudaGetSymbolAddress((void**)&Gb, d_Gb);
    cudaGetSymbolAddress((void**)&sS, d_s);
    cudaGetSymbolAddress((void**)&eE, d_e);
    cudaGetSymbolAddress((void**)&smaxu, d_smaxu);
    cudaGetSymbolAddress((void**)&denom, d_denom);
    cudaGetSymbolAddress((void**)&pooled, d_pooled);

    const int gmM = (NN + 127) / 128;   // 391

    // 1) h = relu(x @ W_fc + b_fc)  -> hp[:, 0:128]
    sgemm_tc<ACT_RELU><<<dim3(gmM, 1), 256>>>(
        x, IN_DIM, nullptr, 0, W_fc, HH, b_fc, hp, H3, NN, IN_DIM);

    // 2) GIN layer 1
    cudaMemsetAsync(agg, 0, (size_t)NN * HH * sizeof(float));
    edge_agg_kernel<<<(EE * 32) / 256, 256>>>(src, dst, hp, H3, agg);
    sgemm_tc<ACT_RELU><<<dim3(gmM, 1), 256>>>(
        hp, H3, agg, HH, W1a, HH, b1a, t, HH, NN, HH);
    sgemm_tc<ACT_RELU><<<dim3(gmM, 1), 256>>>(
        t, HH, nullptr, 0, W1b, HH, b1b, hp + HH, H3, NN, HH);

    // 3) GIN layer 2
    cudaMemsetAsync(agg, 0, (size_t)NN * HH * sizeof(float));
    edge_agg_kernel<<<(EE * 32) / 256, 256>>>(src, dst, hp + HH, H3, agg);
    sgemm_tc<ACT_RELU><<<dim3(gmM, 1), 256>>>(
        hp + HH, H3, agg, HH, W2a, HH, b2a, t, HH, NN, HH);
    sgemm_tc<ACT_RELU><<<dim3(gmM, 1), 256>>>(
        t, HH, nullptr, 0, W2b, HH, b2b, hp + 2 * HH, H3, NN, HH);

    // 4) gated attention scores
    sgemm_tc<ACT_TANH><<<dim3(gmM, 3), 256>>>(
        hp, H3, nullptr, 0, Wa, H3, ba, Ga, H3, NN, H3);
    sgemm_tc<ACT_SIGM><<<dim3(gmM, 3), 256>>>(
        hp, H3, nullptr, 0, Wb, H3, bb, Gb, H3, NN, H3);
    score_kernel<<<(NN * 32 + 255) / 256, 256>>>(Ga, Gb, Wc, bc, sS);

    // 5) segment softmax + weighted pooling
    cudaMemsetAsync(smaxu, 0, GG * sizeof(unsigned));
    cudaMemsetAsync(denom, 0, GG * sizeof(float));
    cudaMemsetAsync(pooled, 0, GG * H3 * sizeof(float));
    segmax_kernel<<<(NN + 255) / 256, 256>>>(sS, batch, smaxu);
    expsum_kernel<<<(NN + 255) / 256, 256>>>(sS, batch, smaxu, eE, denom);
    pool_kernel<<<(NN + PROWS - 1) / PROWS, H3>>>(hp, eE, denom, batch, pooled);

    // 6) head
    head_kernel<<<1, H3>>>(pooled, Wr, br, Wk, bk, out);
}

// round 3
// speedup vs baseline: 2.9551x; 1.0201x over previous
#include <cuda_runtime.h>
#include <cuda_bf16.h>
#include <math.h>

// Problem constants (fixed by the dataset)
#define NN 50000
#define EE 800000
#define GG 8
#define IN_DIM 1792
#define HH 128
#define H3 384

// ---------------- scratch (static device memory; no allocs allowed) ----------------
__device__ float d_hp[(size_t)NN * H3];     // [h | h1 | h2]
__device__ float d_agg[(size_t)NN * HH];
__device__ float d_t[(size_t)NN * HH];
__device__ float d_Ga[(size_t)NN * H3];     // tanh(hp@Wa+ba)
__device__ float d_s[NN];
__device__ float d_e[NN];
__device__ unsigned d_smaxu[GG];
__device__ float d_denom[GG];
__device__ float d_pooled[GG * H3];
// CSR scratch
__device__ int d_cnt[NN];
__device__ int d_off[NN + 1];
__device__ int d_cur[NN];
__device__ int d_ceid[EE];

#define ACT_NONE 0
#define ACT_RELU 1
#define ACT_TANH 2
#define ACT_SIGM 3

// ---------------- tf32 tensor-core SGEMM ----------------
__device__ __forceinline__ unsigned f2tf(float x) {
    unsigned r;
    asm("cvt.rna.tf32.f32 %0, %1;" : "=r"(r) : "f"(x));
    return r;
}

__device__ __forceinline__ void mma_tf32(float* d, const unsigned* a, const unsigned* b) {
    asm volatile(
        "mma.sync.aligned.m16n8k8.row.col.f32.tf32.tf32.f32 "
        "{%0,%1,%2,%3}, {%4,%5,%6,%7}, {%8,%9}, {%0,%1,%2,%3};"
        : "+f"(d[0]), "+f"(d[1]), "+f"(d[2]), "+f"(d[3])
        : "r"(a[0]), "r"(a[1]), "r"(a[2]), "r"(a[3]), "r"(b[0]), "r"(b[1]));
}

#define AP 36    // As row stride (A stored [m][k], 32 k + 4 pad)
#define BP 136   // Bs row stride (B stored [k][n], 128 n + 8 pad)

// Shared main-loop body as a macro-free template; epilogue differs per kernel.

template <int ACT>
__global__ __launch_bounds__(256, 2) void sgemm_tc(
    const float* __restrict__ A, int lda,
    const float* __restrict__ A2, int lda2,
    const float* __restrict__ W, int ldw,
    const float* __restrict__ bias,
    float* __restrict__ C, int ldc,
    int M, int K)
{
    __shared__ unsigned As[128 * AP];
    __shared__ unsigned Bs[32 * BP];

    const int tid = threadIdx.x;
    const int row0 = blockIdx.x * 128;
    const int col0 = blockIdx.y * 128;

    const int warp = tid >> 5;
    const int lane = tid & 31;
    const int group = lane >> 2;
    const int th4 = lane & 3;
    const int wm = (warp & 1) * 64;
    const int wn = (warp >> 1) * 32;

    const int la_r = tid >> 3;
    const int la_c = (tid & 7) * 4;
    const int lb_r = tid >> 5;
    const int lb_c = (tid & 31) * 4;

    float acc[4][4][4];
#pragma unroll
    for (int i = 0; i < 4; i++)
#pragma unroll
        for (int j = 0; j < 4; j++)
#pragma unroll
            for (int v = 0; v < 4; v++) acc[i][j][v] = 0.f;

    const int nk = K >> 5;
    float4 pa[4], pb[4];

#pragma unroll
    for (int i = 0; i < 4; i++) {
        int m = row0 + la_r + i * 32;
        if (m < M) {
            pa[i] = *(const float4*)(A + (size_t)m * lda + la_c);
            if (A2) {
                float4 t2 = *(const float4*)(A2 + (size_t)m * lda2 + la_c);
                pa[i].x += t2.x; pa[i].y += t2.y; pa[i].z += t2.z; pa[i].w += t2.w;
            }
        } else pa[i] = make_float4(0.f, 0.f, 0.f, 0.f);
        pb[i] = *(const float4*)(W + (size_t)(lb_r + i * 8) * ldw + col0 + lb_c);
    }

    for (int kt = 0; kt < nk; kt++) {
        __syncthreads();
#pragma unroll
        for (int i = 0; i < 4; i++) {
            int r = la_r + i * 32;
            As[r * AP + la_c + 0] = f2tf(pa[i].x);
            As[r * AP + la_c + 1] = f2tf(pa[i].y);
            As[r * AP + la_c + 2] = f2tf(pa[i].z);
            As[r * AP + la_c + 3] = f2tf(pa[i].w);
            uint4 bv;
            bv.x = f2tf(pb[i].x); bv.y = f2tf(pb[i].y);
            bv.z = f2tf(pb[i].z); bv.w = f2tf(pb[i].w);
            *(uint4*)&Bs[(lb_r + i * 8) * BP + lb_c] = bv;
        }
        __syncthreads();

        if (kt + 1 < nk) {
            int kb = (kt + 1) * 32;
#pragma unroll
            for (int i = 0; i < 4; i++) {
                int m = row0 + la_r + i * 32;
                if (m < M) {
                    pa[i] = *(const float4*)(A + (size_t)m * lda + kb + la_c);
                    if (A2) {
                        float4 t2 = *(const float4*)(A2 + (size_t)m * lda2 + kb + la_c);
                        pa[i].x += t2.x; pa[i].y += t2.y; pa[i].z += t2.z; pa[i].w += t2.w;
                    }
                } else pa[i] = make_float4(0.f, 0.f, 0.f, 0.f);
                pb[i] = *(const float4*)(W + (size_t)(kb + lb_r + i * 8) * ldw + col0 + lb_c);
            }
        }

#pragma unroll
        for (int ks = 0; ks < 4; ks++) {
            int kk = ks * 8;
            unsigned af[4][4], bf[4][2];
#pragma unroll
            for (int i = 0; i < 4; i++) {
                int mb = (wm + i * 16 + group) * AP + kk + th4;
                af[i][0] = As[mb];
                af[i][1] = As[mb + 8 * AP];
                af[i][2] = As[mb + 4];
                af[i][3] = As[mb + 8 * AP + 4];
            }
#pragma unroll
            for (int j = 0; j < 4; j++) {
                int nb = (kk + th4) * BP + wn + j * 8 + group;
                bf[j][0] = Bs[nb];
                bf[j][1] = Bs[nb + 4 * BP];
            }
#pragma unroll
            for (int i = 0; i < 4; i++)
#pragma unroll
                for (int j = 0; j < 4; j++)
                    mma_tf32(acc[i][j], af[i], bf[j]);
        }
    }

#pragma unroll
    for (int i = 0; i < 4; i++) {
        int r0 = row0 + wm + i * 16 + group;
        int r1 = r0 + 8;
#pragma unroll
        for (int j = 0; j < 4; j++) {
            int cg = col0 + wn + j * 8 + th4 * 2;
            float b0 = bias[cg], b1 = bias[cg + 1];
            float v0 = acc[i][j][0] + b0, v1 = acc[i][j][1] + b1;
            float v2 = acc[i][j][2] + b0, v3 = acc[i][j][3] + b1;
            if (ACT == ACT_RELU) {
                v0 = fmaxf(v0, 0.f); v1 = fmaxf(v1, 0.f);
                v2 = fmaxf(v2, 0.f); v3 = fmaxf(v3, 0.f);
            } else if (ACT == ACT_TANH) {
                v0 = tanhf(v0); v1 = tanhf(v1); v2 = tanhf(v2); v3 = tanhf(v3);
            } else if (ACT == ACT_SIGM) {
                v0 = 1.f / (1.f + expf(-v0)); v1 = 1.f / (1.f + expf(-v1));
                v2 = 1.f / (1.f + expf(-v2)); v3 = 1.f / (1.f + expf(-v3));
            }
            if (r0 < M) { float2 o = make_float2(v0, v1); *(float2*)(C + (size_t)r0 * ldc + cg) = o; }
            if (r1 < M) { float2 o = make_float2(v2, v3); *(float2*)(C + (size_t)r1 * ldc + cg) = o; }
        }
    }
}

// ---------------- gated sigm GEMM with fused score reduction ----------------
// computes v = sigmoid(A@W + bias); s[r] += sum_c v[r,c] * Ga[r,c] * Wc[c]
__global__ __launch_bounds__(256, 2) void sgemm_gate(
    const float* __restrict__ A, int lda,
    const float* __restrict__ W, int ldw,
    const float* __restrict__ bias,
    const float* __restrict__ Ga, int ldga,
    const float* __restrict__ Wc,
    float* __restrict__ sOut,
    int M, int K)
{
    __shared__ unsigned As[128 * AP];
    __shared__ unsigned Bs[32 * BP];

    const int tid = threadIdx.x;
    const int row0 = blockIdx.x * 128;
    const int col0 = blockIdx.y * 128;

    const int warp = tid >> 5;
    const int lane = tid & 31;
    const int group = lane >> 2;
    const int th4 = lane & 3;
    const int wm = (warp & 1) * 64;
    const int wn = (warp >> 1) * 32;

    const int la_r = tid >> 3;
    const int la_c = (tid & 7) * 4;
    const int lb_r = tid >> 5;
    const int lb_c = (tid & 31) * 4;

    float acc[4][4][4];
#pragma unroll
    for (int i = 0; i < 4; i++)
#pragma unroll
        for (int j = 0; j < 4; j++)
#pragma unroll
            for (int v = 0; v < 4; v++) acc[i][j][v] = 0.f;

    const int nk = K >> 5;
    float4 pa[4], pb[4];

#pragma unroll
    for (int i = 0; i < 4; i++) {
        int m = row0 + la_r + i * 32;
        pa[i] = (m < M) ? *(const float4*)(A + (size_t)m * lda + la_c)
                        : make_float4(0.f, 0.f, 0.f, 0.f);
        pb[i] = *(const float4*)(W + (size_t)(lb_r + i * 8) * ldw + col0 + lb_c);
    }

    for (int kt = 0; kt < nk; kt++) {
        __syncthreads();
#pragma unroll
        for (int i = 0; i < 4; i++) {
            int r = la_r + i * 32;
            As[r * AP + la_c + 0] = f2tf(pa[i].x);
            As[r * AP + la_c + 1] = f2tf(pa[i].y);
            As[r * AP + la_c + 2] = f2tf(pa[i].z);
            As[r * AP + la_c + 3] = f2tf(pa[i].w);
            uint4 bv;
            bv.x = f2tf(pb[i].x); bv.y = f2tf(pb[i].y);
            bv.z = f2tf(pb[i].z); bv.w = f2tf(pb[i].w);
            *(uint4*)&Bs[(lb_r + i * 8) * BP + lb_c] = bv;
        }
        __syncthreads();

        if (kt + 1 < nk) {
            int kb = (kt + 1) * 32;
#pragma unroll
            for (int i = 0; i < 4; i++) {
                int m = row0 + la_r + i * 32;
                pa[i] = (m < M) ? *(const float4*)(A + (size_t)m * lda + kb + la_c)
                                : make_float4(0.f, 0.f, 0.f, 0.f);
                pb[i] = *(const float4*)(W + (size_t)(kb + lb_r + i * 8) * ldw + col0 + lb_c);
            }
        }

#pragma unroll
        for (int ks = 0; ks < 4; ks++) {
            int kk = ks * 8;
            unsigned af[4][4], bf[4][2];
#pragma unroll
            for (int i = 0; i < 4; i++) {
                int mb = (wm + i * 16 + group) * AP + kk + th4;
                af[i][0] = As[mb];
                af[i][1] = As[mb + 8 * AP];
                af[i][2] = As[mb + 4];
                af[i][3] = As[mb + 8 * AP + 4];
            }
#pragma unroll
            for (int j = 0; j < 4; j++) {
                int nb = (kk + th4) * BP + wn + j * 8 + group;
                bf[j][0] = Bs[nb];
                bf[j][1] = Bs[nb + 4 * BP];
            }
#pragma unroll
            for (int i = 0; i < 4; i++)
#pragma unroll
                for (int j = 0; j < 4; j++)
                    mma_tf32(acc[i][j], af[i], bf[j]);
        }
    }

    // epilogue: gated score partial per row, quad-reduce, atomicAdd
#pragma unroll
    for (int i = 0; i < 4; i++) {
        int r0 = row0 + wm + i * 16 + group;
        int r1 = r0 + 8;
        float p0 = 0.f, p1 = 0.f;
#pragma unroll
        for (int j = 0; j < 4; j++) {
            int cg = col0 + wn + j * 8 + th4 * 2;
            float b0 = bias[cg], b1 = bias[cg + 1];
            float w0 = Wc[cg], w1 = Wc[cg + 1];
            float v0 = 1.f / (1.f + expf(-(acc[i][j][0] + b0)));
            float v1 = 1.f / (1.f + expf(-(acc[i][j][1] + b1)));
            float v2 = 1.f / (1.f + expf(-(acc[i][j][2] + b0)));
            float v3 = 1.f / (1.f + expf(-(acc[i][j][3] + b1)));
            if (r0 < M) {
                float2 g = *(const float2*)(Ga + (size_t)r0 * ldga + cg);
                p0 += v0 * g.x * w0 + v1 * g.y * w1;
            }
            if (r1 < M) {
                float2 g = *(const float2*)(Ga + (size_t)r1 * ldga + cg);
                p1 += v2 * g.x * w0 + v3 * g.y * w1;
            }
        }
        p0 += __shfl_xor_sync(0xffffffffu, p0, 1);
        p0 += __shfl_xor_sync(0xffffffffu, p0, 2);
        p1 += __shfl_xor_sync(0xffffffffu, p1, 1);
        p1 += __shfl_xor_sync(0xffffffffu, p1, 2);
        if (th4 == 0) {
            if (r0 < M) atomicAdd(&sOut[r0], p0);
            if (r1 < M) atomicAdd(&sOut[r1], p1);
        }
    }
}

// ---------------- CSR build ----------------
__global__ __launch_bounds__(256) void hist_kernel(
    const int* __restrict__ dst, int* __restrict__ cnt)
{
    int e = blockIdx.x * blockDim.x + threadIdx.x;
    if (e < EE) atomicAdd(&cnt[dst[e]], 1);
}

__global__ __launch_bounds__(1024) void scan_kernel(
    const int* __restrict__ cnt, int* __restrict__ off, int* __restrict__ cur)
{
    __shared__ int part[1024];
    const int tid = threadIdx.x;
    const int CH = (NN + 1023) / 1024;   // 49
    const int base = tid * CH;
    int s = 0;
    for (int i = 0; i < CH; i++) {
        int idx = base + i;
        if (idx < NN) s += cnt[idx];
    }
    part[tid] = s;
    __syncthreads();
    // inclusive Hillis-Steele scan
    for (int o = 1; o < 1024; o <<= 1) {
        int v = (tid >= o) ? part[tid - o] : 0;
        __syncthreads();
        part[tid] += v;
        __syncthreads();
    }
    int run = (tid == 0) ? 0 : part[tid - 1];
    for (int i = 0; i < CH; i++) {
        int idx = base + i;
        if (idx < NN) {
            off[idx] = run;
            cur[idx] = run;
            run += cnt[idx];
        }
    }
    if (tid == 1023) off[NN] = run;
}

__global__ __launch_bounds__(256) void scatter_kernel(
    const int* __restrict__ src, const int* __restrict__ dst,
    int* __restrict__ cur, int* __restrict__ ceid)
{
    int e = blockIdx.x * blockDim.x + threadIdx.x;
    if (e >= EE) return;
    int p = atomicAdd(&cur[dst[e]], 1);
    ceid[p] = src[e];
}

// ---------------- CSR aggregation: agg[n] = sum_{e in n} h[src_e] ----------------
__global__ __launch_bounds__(256) void csr_agg_kernel(
    const int* __restrict__ off, const int* __restrict__ ceid,
    const float* __restrict__ h, int ldh, float* __restrict__ agg)
{
    int node = (blockIdx.x * blockDim.x + threadIdx.x) >> 5;
    int lane = threadIdx.x & 31;
    if (node >= NN) return;
    int b = off[node], e2 = off[node + 1];
    float ax = 0.f, ay = 0.f, az = 0.f, aw = 0.f;
    int i = b;
    for (; i + 4 <= e2; i += 4) {
        int s0 = ceid[i], s1 = ceid[i + 1], s2 = ceid[i + 2], s3 = ceid[i + 3];
        float4 v0 = *(const float4*)(h + (size_t)s0 * ldh + lane * 4);
        float4 v1 = *(const float4*)(h + (size_t)s1 * ldh + lane * 4);
        float4 v2 = *(const float4*)(h + (size_t)s2 * ldh + lane * 4);
        float4 v3 = *(const float4*)(h + (size_t)s3 * ldh + lane * 4);
        ax += (v0.x + v1.x) + (v2.x + v3.x);
        ay += (v0.y + v1.y) + (v2.y + v3.y);
        az += (v0.z + v1.z) + (v2.z + v3.z);
        aw += (v0.w + v1.w) + (v2.w + v3.w);
    }
    for (; i < e2; i++) {
        int s0 = ceid[i];
        float4 v0 = *(const float4*)(h + (size_t)s0 * ldh + lane * 4);
        ax += v0.x; ay += v0.y; az += v0.z; aw += v0.w;
    }
    float4 o = make_float4(ax, ay, az, aw);
    *(float4*)(agg + (size_t)node * HH + lane * 4) = o;
}

// ---------------- softmax helpers ----------------
__device__ __forceinline__ unsigned fenc(float v) {
    unsigned b = __float_as_uint(v);
    return (b & 0x80000000u) ? ~b : (b | 0x80000000u);
}
__device__ __forceinline__ float fdec(unsigned u) {
    return (u & 0x80000000u) ? __uint_as_float(u & 0x7fffffffu) : __uint_as_float(~u);
}

__global__ __launch_bounds__(256) void segmax_kernel(
    const float* __restrict__ s, const int* __restrict__ batch, unsigned* __restrict__ smaxu)
{
    __shared__ unsigned sm[GG];
    if (threadIdx.x < GG) sm[threadIdx.x] = 0u;
    __syncthreads();
    int i = blockIdx.x * blockDim.x + threadIdx.x;
    if (i < NN) atomicMax(&sm[batch[i]], fenc(s[i]));
    __syncthreads();
    if (threadIdx.x < GG) atomicMax(&smaxu[threadIdx.x], sm[threadIdx.x]);
}

__global__ __launch_bounds__(256) void expsum_kernel(
    const float* __restrict__ s, const int* __restrict__ batch,
    const unsigned* __restrict__ smaxu, float* __restrict__ e, float* __restrict__ denom)
{
    __shared__ float sd[GG];
    if (threadIdx.x < GG) sd[threadIdx.x] = 0.f;
    __syncthreads();
    int i = blockIdx.x * blockDim.x + threadIdx.x;
    if (i < NN) {
        int g = batch[i];
        float v = expf(s[i] - fdec(smaxu[g]));
        e[i] = v;
        atomicAdd(&sd[g], v);
    }
    __syncthreads();
    if (threadIdx.x < GG) atomicAdd(&denom[threadIdx.x], sd[threadIdx.x]);
}

// ---------------- pooled[g][c] = sum_i in g  hp[i][c] * w[i] ----------------
#define PROWS 128
__global__ __launch_bounds__(H3) void pool_kernel(
    const float* __restrict__ hp, const float* __restrict__ e,
    const float* __restrict__ denom, const int* __restrict__ batch,
    float* __restrict__ pooled)
{
    __shared__ float wsh[PROWS];
    __shared__ int gsh[PROWS];
    int r0 = blockIdx.x * PROWS;
    int nr = min(PROWS, NN - r0);
    int tid = threadIdx.x;
    if (tid < nr) {
        int g = batch[r0 + tid];
        gsh[tid] = g;
        wsh[tid] = e[r0 + tid] / denom[g];
    }
    __syncthreads();
    int c = tid;
    float acc = 0.f;
    int curg = gsh[0];
    for (int r = 0; r < nr; r++) {
        int g = gsh[r];
        if (g != curg) {
            atomicAdd(&pooled[curg * H3 + c], acc);
            acc = 0.f;
            curg = g;
        }
        acc += hp[(size_t)(r0 + r) * H3 + c] * wsh[r];
    }
    atomicAdd(&pooled[curg * H3 + c], acc);
}

// ---------------- head ----------------
__global__ __launch_bounds__(H3) void head_kernel(
    const float* __restrict__ pooled, const float* __restrict__ Wr,
    const float* __restrict__ br, const float* __restrict__ Wk,
    const float* __restrict__ bk, float* __restrict__ out)
{
    __shared__ float ps[GG * H3];
    __shared__ float rs[GG * H3];
    int tid = threadIdx.x;
    for (int i = tid; i < GG * H3; i += H3) ps[i] = pooled[i];
    __syncthreads();
    int c = tid;
    float bias = br[c];
#pragma unroll 1
    for (int g = 0; g < GG; g++) {
        float a = 0.f;
        for (int k = 0; k < H3; k++) a = fmaf(ps[g * H3 + k], Wr[(size_t)k * H3 + c], a);
        rs[g * H3 + c] = fmaxf(a + bias, 0.f);
    }
    __syncthreads();
    int warp = tid >> 5, lane = tid & 31;
    if (warp < GG) {
        float a = 0.f;
        for (int j = lane; j < H3; j += 32) a += rs[warp * H3 + j] * Wk[j];
#pragma unroll
        for (int o = 16; o; o >>= 1) a += __shfl_xor_sync(0xffffffffu, a, o);
        if (lane == 0) out[warp] = a + bk[0];
    }
}

// ---------------- host ----------------
extern "C" void kernel_launch(void* const* d_in, const int* in_sizes, int n_in,
                              void* d_out, int out_size)
{
    const float* x      = (const float*)d_in[0];
    const int*   eidx   = (const int*)d_in[1];
    const int*   batch  = (const int*)d_in[2];
    const float* W_fc   = (const float*)d_in[3];
    const float* b_fc   = (const float*)d_in[4];
    const float* W1a    = (const float*)d_in[5];
    const float* b1a    = (const float*)d_in[6];
    const float* W1b    = (const float*)d_in[7];
    const float* b1b    = (const float*)d_in[8];
    const float* W2a    = (const float*)d_in[9];
    const float* b2a    = (const float*)d_in[10];
    const float* W2b    = (const float*)d_in[11];
    const float* b2b    = (const float*)d_in[12];
    const float* Wa     = (const float*)d_in[13];
    const float* ba     = (const float*)d_in[14];
    const float* Wb     = (const float*)d_in[15];
    const float* bb     = (const float*)d_in[16];
    const float* Wc     = (const float*)d_in[17];
    // d_in[18] = bc (dropped: softmax shift-invariant)
    const float* Wr     = (const float*)d_in[19];
    const float* br     = (const float*)d_in[20];
    const float* Wk     = (const float*)d_in[21];
    const float* bk     = (const float*)d_in[22];
    float* out = (float*)d_out;

    const int* src = eidx;
    const int* dst = eidx + EE;

    float *hp, *agg, *t, *Ga, *sS, *eE, *denom, *pooled;
    unsigned* smaxu;
    int *cnt, *off, *cur, *ceid;
    cudaGetSymbolAddress((void**)&hp, d_hp);
    cudaGetSymbolAddress((void**)&agg, d_agg);
    cudaGetSymbolAddress((void**)&t, d_t);
    cudaGetSymbolAddress((void**)&Ga, d_Ga);
    cudaGetSymbolAddress((void**)&sS, d_s);
    cudaGetSymbolAddress((void**)&eE, d_e);
    cudaGetSymbolAddress((void**)&smaxu, d_smaxu);
    cudaGetSymbolAddress((void**)&denom, d_denom);
    cudaGetSymbolAddress((void**)&pooled, d_pooled);
    cudaGetSymbolAddress((void**)&cnt, d_cnt);
    cudaGetSymbolAddress((void**)&off, d_off);
    cudaGetSymbolAddress((void**)&cur, d_cur);
    cudaGetSymbolAddress((void**)&ceid, d_ceid);

    const int gmM = (NN + 127) / 128;   // 391

    // --- CSR build (once; reused by both GIN layers) ---
    cudaMemsetAsync(cnt, 0, NN * sizeof(int));
    hist_kernel<<<(EE + 255) / 256, 256>>>(dst, cnt);
    scan_kernel<<<1, 1024>>>(cnt, off, cur);
    scatter_kernel<<<(EE + 255) / 256, 256>>>(src, dst, cur, ceid);

    // 1) h = relu(x @ W_fc + b_fc)  -> hp[:, 0:128]
    sgemm_tc<ACT_RELU><<<dim3(gmM, 1), 256>>>(
        x, IN_DIM, nullptr, 0, W_fc, HH, b_fc, hp, H3, NN, IN_DIM);

    // 2) GIN layer 1
    csr_agg_kernel<<<(NN * 32 + 255) / 256, 256>>>(off, ceid, hp, H3, agg);
    sgemm_tc<ACT_RELU><<<dim3(gmM, 1), 256>>>(
        hp, H3, agg, HH, W1a, HH, b1a, t, HH, NN, HH);
    sgemm_tc<ACT_RELU><<<dim3(gmM, 1), 256>>>(
        t, HH, nullptr, 0, W1b, HH, b1b, hp + HH, H3, NN, HH);

    // 3) GIN layer 2
    csr_agg_kernel<<<(NN * 32 + 255) / 256, 256>>>(off, ceid, hp + HH, H3, agg);
    sgemm_tc<ACT_RELU><<<dim3(gmM, 1), 256>>>(
        hp + HH, H3, agg, HH, W2a, HH, b2a, t, HH, NN, HH);
    sgemm_tc<ACT_RELU><<<dim3(gmM, 1), 256>>>(
        t, HH, nullptr, 0, W2b, HH, b2b, hp + 2 * HH, H3, NN, HH);

    // 4) gated attention scores: Ga = tanh(hp@Wa+ba); s = sum sigm(hp@Wb+bb)*Ga*Wc
    cudaMemsetAsync(sS, 0, NN * sizeof(float));
    sgemm_tc<ACT_TANH><<<dim3(gmM, 3), 256>>>(
        hp, H3, nullptr, 0, Wa, H3, ba, Ga, H3, NN, H3);
    sgemm_gate<<<dim3(gmM, 3), 256>>>(
        hp, H3, Wb, H3, bb, Ga, H3, Wc, sS, NN, H3);

    // 5) segment softmax + weighted pooling
    cudaMemsetAsync(smaxu, 0, GG * sizeof(unsigned));
    cudaMemsetAsync(denom, 0, GG * sizeof(float));
    cudaMemsetAsync(pooled, 0, GG * H3 * sizeof(float));
    segmax_kernel<<<(NN + 255) / 256, 256>>>(sS, batch, smaxu);
    expsum_kernel<<<(NN + 255) / 256, 256>>>(sS, batch, smaxu, eE, denom);
    pool_kernel<<<(NN + PROWS - 1) / PROWS, H3>>>(hp, eE, denom, batch, pooled);

    // 6) head
    head_kernel<<<1, H3>>>(pooled, Wr, br, Wk, bk, out);
}